// round 6
// baseline (speedup 1.0000x reference)
#include <cuda_runtime.h>
#include <cstdint>

// Shapes (fixed):
//   x      [B=4][Cin=64][12][12][12][12]
//   weight [Cin=64][Cout=64][3][3][3][3]
//   bias   [64]
//   out    [B=4][Cout=64][25][25][25][25]   (z = 2m+p, stride 2, K=3)

#define B_      4
#define CIN     64
#define COUT    64
#define NTAPS   81
#define XCH_STRIDE 20736          // 12^4
#define OCH_STRIDE 390625         // 25^4
#define OSP3   15625              // 25^3
#define ODIM   25

// Pre-transposed, pre-duplicated weights: g_wt2[tap][i][o] = {w, w}. 2.66 MB.
__device__ float2 g_wt2[NTAPS * CIN * COUT];

__global__ void wt_prep_kernel(const float* __restrict__ w) {
    int idx = blockIdx.x * 256 + threadIdx.x;
    if (idx >= NTAPS * CIN * COUT) return;
    int t = idx / (CIN * COUT);
    int r = idx - t * (CIN * COUT);
    int i = r >> 6;
    int o = r & 63;
    float v = w[(i * COUT + o) * NTAPS + t];
    g_wt2[idx] = make_float2(v, v);
}

#define FF2(a, xx, ww) \
    asm("fma.rn.f32x2 %0, %1, %2, %0;" : "+l"(a) : "l"(xx), "l"(ww))

__global__ __launch_bounds__(128, 4)
void ct4d_kernel(const float* __restrict__ x,
                 const float* __restrict__ bias,
                 float* __restrict__ out) {
    __shared__ float  sx[32][128];    // 16 KB: [k_local][m]
    __shared__ float2 swd[64][64];    // 32 KB: [k][n] duplicated pairs

    // parity class
    const int pc = blockIdx.y;
    const int p1 = (pc >> 3) & 1, p2 = (pc >> 2) & 1, p3 = (pc >> 1) & 1, p4 = pc & 1;
    const int n1 = 13 - p1, n2 = 13 - p2, n3 = 13 - p3, n4 = 13 - p4;
    const int csz = n1 * n2 * n3 * n4;
    const int base = blockIdx.x * 128;
    if (base >= csz) return;          // uniform over block

    const int t = threadIdx.x;
    const int b = blockIdx.z;

    // this thread's staging point (local m index == t)
    const int lin = base + t;
    const bool inr = lin < csz;
    int l = inr ? lin : 0;
    const int sm4 = l % n4; l /= n4;
    const int sm3 = l % n3; l /= n3;
    const int sm2 = l % n2; l /= n2;
    const int sm1 = l;

    // GEMM micro-tile: 8 m-points (4 pairs) x 8 n
    const int m0 = (t & 15) << 3;
    const int n0 = (t >> 4) << 3;

    unsigned long long acc[4][8];
    #pragma unroll
    for (int nn = 0; nn < 8; nn++) {
        float bv = __ldg(bias + n0 + nn);
        unsigned long long bp;
        asm("mov.b64 %0, {%1, %1};" : "=l"(bp) : "f"(bv));
        #pragma unroll
        for (int mp = 0; mp < 4; mp++) acc[mp][nn] = bp;
    }

    const float* xb = x + (size_t)b * (CIN * XCH_STRIDE);
    const int t1max = 1 - p1, t2max = 1 - p2, t3max = 1 - p3, t4max = 1 - p4;

    for (int t1 = 0; t1 <= t1max; t1++)
    for (int t2 = 0; t2 <= t2max; t2++)
    for (int t3 = 0; t3 <= t3max; t3++)
    for (int t4 = 0; t4 <= t4max; t4++) {
        const int k1 = p1 + 2 * t1, k2 = p2 + 2 * t2;
        const int k3 = p3 + 2 * t3, k4 = p4 + 2 * t4;
        const int tap = ((k1 * 3 + k2) * 3 + k3) * 3 + k4;
        const int l1 = sm1 - t1, l2 = sm2 - t2, l3 = sm3 - t3, l4 = sm4 - t4;
        const bool xv = inr && (unsigned)l1 < 12u && (unsigned)l2 < 12u
                            && (unsigned)l3 < 12u && (unsigned)l4 < 12u;
        const float* xp = xb + (((l1 * 12 + l2) * 12 + l3) * 12 + l4);

        __syncthreads();   // protect swd/sx from previous iteration's readers
        // stage duplicated weight slice: 2048 float4 = 32 KB
        {
            const float4* src = (const float4*)(g_wt2 + (size_t)tap * (CIN * COUT));
            float4* dst = (float4*)swd;
            #pragma unroll
            for (int s = 0; s < 16; s++)
                dst[t + s * 128] = src[t + s * 128];
        }
        // stage x half 0 (i = 0..31), zeros where gather is out of range
        #pragma unroll 8
        for (int i = 0; i < 32; i++)
            sx[i][t] = xv ? __ldg(xp + (size_t)i * XCH_STRIDE) : 0.0f;
        __syncthreads();

        // GEMM half 0
        #pragma unroll 4
        for (int k = 0; k < 32; k++) {
            const ulonglong2 xA = *(const ulonglong2*)&sx[k][m0];
            const ulonglong2 xB = *(const ulonglong2*)&sx[k][m0 + 4];
            const ulonglong2 w0 = *(const ulonglong2*)&swd[k][n0];
            const ulonglong2 w1 = *(const ulonglong2*)&swd[k][n0 + 2];
            const ulonglong2 w2 = *(const ulonglong2*)&swd[k][n0 + 4];
            const ulonglong2 w3 = *(const ulonglong2*)&swd[k][n0 + 6];
            #define ROW(mp, xs) \
                FF2(acc[mp][0], xs, w0.x); FF2(acc[mp][1], xs, w0.y); \
                FF2(acc[mp][2], xs, w1.x); FF2(acc[mp][3], xs, w1.y); \
                FF2(acc[mp][4], xs, w2.x); FF2(acc[mp][5], xs, w2.y); \
                FF2(acc[mp][6], xs, w3.x); FF2(acc[mp][7], xs, w3.y);
            ROW(0, xA.x) ROW(1, xA.y) ROW(2, xB.x) ROW(3, xB.y)
        }
        __syncthreads();

        // stage x half 1 (i = 32..63)
        #pragma unroll 8
        for (int i = 0; i < 32; i++)
            sx[i][t] = xv ? __ldg(xp + (size_t)(i + 32) * XCH_STRIDE) : 0.0f;
        __syncthreads();

        // GEMM half 1
        #pragma unroll 4
        for (int k = 0; k < 32; k++) {
            const ulonglong2 xA = *(const ulonglong2*)&sx[k][m0];
            const ulonglong2 xB = *(const ulonglong2*)&sx[k][m0 + 4];
            const ulonglong2 w0 = *(const ulonglong2*)&swd[k + 32][n0];
            const ulonglong2 w1 = *(const ulonglong2*)&swd[k + 32][n0 + 2];
            const ulonglong2 w2 = *(const ulonglong2*)&swd[k + 32][n0 + 4];
            const ulonglong2 w3 = *(const ulonglong2*)&swd[k + 32][n0 + 6];
            ROW(0, xA.x) ROW(1, xA.y) ROW(2, xB.x) ROW(3, xB.y)
            #undef ROW
        }
    }

    // epilogue: thread owns local points m0..m0+7 (pairs), Cout n0..n0+7
    float* obase = out + (size_t)b * COUT * OCH_STRIDE + (size_t)n0 * OCH_STRIDE;
    #pragma unroll
    for (int mp = 0; mp < 4; mp++) {
        #pragma unroll
        for (int half = 0; half < 2; half++) {
            const int linp = base + m0 + 2 * mp + half;
            if (linp >= csz) continue;
            int ll = linp;
            const int q4 = ll % n4; ll /= n4;
            const int q3 = ll % n3; ll /= n3;
            const int q2 = ll % n2; ll /= n2;
            const int q1 = ll;
            const size_t sof = (size_t)(2 * q1 + p1) * OSP3
                             + (size_t)(2 * q2 + p2) * (ODIM * ODIM)
                             + (size_t)(2 * q3 + p3) * ODIM
                             + (size_t)(2 * q4 + p4);
            float* op = obase + sof;
            #pragma unroll
            for (int nn = 0; nn < 8; nn++) {
                const unsigned long long a = acc[mp][nn];
                const unsigned u = half ? (unsigned)(a >> 32)
                                        : (unsigned)(a & 0xffffffffu);
                op[(size_t)nn * OCH_STRIDE] = __uint_as_float(u);
            }
        }
    }
}

extern "C" void kernel_launch(void* const* d_in, const int* in_sizes, int n_in,
                              void* d_out, int out_size) {
    const float* x    = (const float*)d_in[0];
    const float* w    = (const float*)d_in[1];
    const float* bias = (const float*)d_in[2];
    float* out        = (float*)d_out;

    const int wtot = NTAPS * CIN * COUT;  // 331776
    wt_prep_kernel<<<(wtot + 255) / 256, 256>>>(w);

    // grid.x covers the largest parity class: ceil(13^4 / 128) = 224
    dim3 grid(224, 16, B_);
    ct4d_kernel<<<grid, 128>>>(x, bias, out);
}